// round 2
// baseline (speedup 1.0000x reference)
#include <cuda_runtime.h>
#include <math.h>
#include <float.h>

#define NBATCH 8
#define SEQ    4096
#define DIM    128
#define NHASH  8
#define NBUCK  64
#define NCHUNK 512
#define NSLOT  32768
#define CHUNK  64
#define QKSCALE 0.08838834764831843f
#define MNEG   (-3.402823466e38f)

__device__ int   g_buckets[NBATCH*NHASH*SEQ];
__device__ int   g_counts [NBATCH*512];
__device__ int   g_bstart [NBATCH*512];
__device__ int   g_st     [NBATCH*NSLOT];
__device__ int   g_sb     [NBATCH*NSLOT];
__device__ int   g_slotof [NBATCH*SEQ*NHASH];
__device__ int   g_L      [NBATCH*SEQ*NHASH];
__device__ float g_lse    [NBATCH*NSLOT];
__device__ float g_bo     [(size_t)NBATCH*NSLOT*DIM];

// ---------------- K1: LSH hashing ----------------
__global__ void k_hash(const float* __restrict__ qk, const float* __restrict__ rot) {
    extern __shared__ float sm[];
    float* srot = sm;            // 32768
    float* sq   = sm + 32768;    // 4096
    int tid = threadIdx.x;
    for (int i = tid; i < 32768/4; i += 256)
        ((float4*)srot)[i] = ((const float4*)rot)[i];
    int tok0 = blockIdx.x * 32;
    int b = tok0 >> 12;
    int s0 = tok0 & 4095;
    const float* qbase = qk + (size_t)tok0 * DIM;
    for (int i = tid; i < (32*128)/4; i += 256)
        ((float4*)sq)[i] = ((const float4*)qbase)[i];
    __syncthreads();

    int ngrp = tid & 31, tgrp = tid >> 5;
    int hub = ngrp * 8, tb = tgrp * 4;
    float acc[4][8];
#pragma unroll
    for (int i = 0; i < 4; i++)
#pragma unroll
        for (int j = 0; j < 8; j++) acc[i][j] = 0.f;

#pragma unroll 4
    for (int d = 0; d < 128; d++) {
        float4 r0 = *(const float4*)(srot + d*256 + hub);
        float4 r1 = *(const float4*)(srot + d*256 + hub + 4);
#pragma unroll
        for (int i = 0; i < 4; i++) {
            float q = sq[(tb+i)*128 + d];
            acc[i][0] += q*r0.x; acc[i][1] += q*r0.y; acc[i][2] += q*r0.z; acc[i][3] += q*r0.w;
            acc[i][4] += q*r1.x; acc[i][5] += q*r1.y; acc[i][6] += q*r1.z; acc[i][7] += q*r1.w;
        }
    }
    int h = ngrp >> 2, k = ngrp & 3;
#pragma unroll
    for (int i = 0; i < 4; i++) {
        float bv = -1.0f; int bi = 0;
#pragma unroll
        for (int j = 0; j < 8; j++) {
            float r = acc[i][j];
            float a = fabsf(r);
            int n  = k*8 + j;
            int ci = (r < 0.f) ? (n + 32) : n;
            if (a > bv || (a == bv && ci < bi)) { bv = a; bi = ci; }
        }
#pragma unroll
        for (int off = 1; off <= 2; off <<= 1) {
            float ov = __shfl_xor_sync(0xffffffffu, bv, off);
            int   oi = __shfl_xor_sync(0xffffffffu, bi, off);
            if (ov > bv || (ov == bv && oi < bi)) { bv = ov; bi = oi; }
        }
        if (k == 0)
            g_buckets[((b*NHASH + h) * SEQ) + s0 + tb + i] = h*NBUCK + bi;
    }
}

// ---------------- K2: counting sort ----------------
__global__ void k_hist() {
    int i = blockIdx.x * 256 + threadIdx.x;
    int b = i >> 15;
    atomicAdd(&g_counts[b*512 + g_buckets[i]], 1);
}

__global__ void k_prefix() {
    __shared__ int sc[512];
    int b = blockIdx.x, t = threadIdx.x;
    int v = g_counts[b*512 + t];
    sc[t] = v;
    __syncthreads();
    for (int off = 1; off < 512; off <<= 1) {
        int add = (t >= off) ? sc[t-off] : 0;
        __syncthreads();
        sc[t] += add;
        __syncthreads();
    }
    g_bstart[b*512 + t] = sc[t] - v;
}

__global__ void k_scatter() {
    extern __shared__ int sh[];            // [64][257]
    int b = blockIdx.x >> 3, h = blockIdx.x & 7;
    int t = threadIdx.x;
    const int* bk = &g_buckets[(b*NHASH + h) * SEQ];
    for (int i = t; i < 64*257; i += 256) sh[i] = 0;
    __syncthreads();
    int p0 = t * 16;
#pragma unroll
    for (int q = 0; q < 16; q++) {
        int c = bk[p0 + q] - h*NBUCK;
        sh[c*257 + t]++;
    }
    __syncthreads();
    if (t < 64) {
        int run = g_bstart[b*512 + h*NBUCK + t];
        for (int u = 0; u < 256; u++) {
            int v = sh[t*257 + u];
            sh[t*257 + u] = run;
            run += v;
        }
    }
    __syncthreads();
#pragma unroll
    for (int q = 0; q < 16; q++) {
        int pos = p0 + q;
        int Bg  = bk[pos];
        int c   = Bg - h*NBUCK;
        int slot = sh[c*257 + t]++;
        g_st[b*NSLOT + slot] = pos;
        g_sb[b*NSLOT + slot] = Bg;
        g_slotof[(b*SEQ + pos)*NHASH + h] = slot;
        g_L     [(b*SEQ + pos)*NHASH + h] = Bg*512 + (slot >> 6);
    }
}

// ---------------- K3: chunked attention ----------------
__global__ __launch_bounds__(256, 1) void k_attn(const float* __restrict__ qk,
                                                 const float* __restrict__ vin) {
    extern __shared__ float smf[];
    float* QT   = smf;                 // [128][68]
    float* KT   = QT + 128*68;         // [128][132]
    float* SV   = KT + 128*132;        // [128][132]
    float* SP   = SV + 128*132;        // [64][132]
    int*   posq = (int*)(SP + 64*132);
    int*   posk = posq + 64;
    int*   bqv  = posk + 128;
    int*   bkv  = bqv + 64;
    int*   sLq  = bkv + 128;           // 64*8
    int*   sLk  = sLq + 512;           // 128*8
    float* ssq  = (float*)(sLk + 1024);// 256
    float* rsc  = ssq + 256;           // 128

    int bid = blockIdx.x;
    int b = bid >> 9;
    int c = bid & 511;
    int cprev = (c + NCHUNK - 1) & 511;
    int tid = threadIdx.x;

    if (tid < 64) {
        int slot = c*CHUNK + tid;
        int pos  = g_st[b*NSLOT + slot];
        posq[tid] = pos;
        bqv[tid]  = g_sb[b*NSLOT + slot];
        const int4* lp = (const int4*)&g_L[(b*SEQ + pos)*NHASH];
        ((int4*)(sLq + tid*8))[0] = lp[0];
        ((int4*)(sLq + tid*8))[1] = lp[1];
    } else if (tid < 192) {
        int z = tid - 64;
        int slot = (z < 64) ? (c*CHUNK + z) : (cprev*CHUNK + (z - 64));
        int pos  = g_st[b*NSLOT + slot];
        posk[z] = pos;
        bkv[z]  = g_sb[b*NSLOT + slot];
        const int4* lp = (const int4*)&g_L[(b*SEQ + pos)*NHASH];
        ((int4*)(sLk + z*8))[0] = lp[0];
        ((int4*)(sLk + z*8))[1] = lp[1];
    }
    __syncthreads();

    {   // q transposed + pre-scaled
        int s = tid >> 2, part = tid & 3;
        const float* src = qk + ((size_t)b*SEQ + posq[s])*DIM + part*32;
#pragma unroll
        for (int k4 = 0; k4 < 8; k4++) {
            float4 q4 = ((const float4*)src)[k4];
            int d = part*32 + k4*4;
            QT[(d+0)*68 + s] = q4.x * QKSCALE;
            QT[(d+1)*68 + s] = q4.y * QKSCALE;
            QT[(d+2)*68 + s] = q4.z * QKSCALE;
            QT[(d+3)*68 + s] = q4.w * QKSCALE;
        }
    }
    {   // k transposed + partial sumsq
        int z = tid >> 1, half = tid & 1;
        const float* src = qk + ((size_t)b*SEQ + posk[z])*DIM + half*64;
        float ss = 0.f;
#pragma unroll
        for (int k4 = 0; k4 < 16; k4++) {
            float4 kv = ((const float4*)src)[k4];
            int d = half*64 + k4*4;
            KT[(d+0)*132 + z] = kv.x;
            KT[(d+1)*132 + z] = kv.y;
            KT[(d+2)*132 + z] = kv.z;
            KT[(d+3)*132 + z] = kv.w;
            ss += kv.x*kv.x + kv.y*kv.y + kv.z*kv.z + kv.w*kv.w;
        }
        ssq[z*2 + half] = ss;
    }
    {   // v row-major
        int z = tid >> 1, half = tid & 1;
        const float* src = vin + ((size_t)b*SEQ + posk[z])*DIM + half*64;
#pragma unroll
        for (int k4 = 0; k4 < 16; k4++) {
            float4 vv = ((const float4*)src)[k4];
            int d = half*64 + k4*4;
            SV[z*132 + d + 0] = vv.x;
            SV[z*132 + d + 1] = vv.y;
            SV[z*132 + d + 2] = vv.z;
            SV[z*132 + d + 3] = vv.w;
        }
    }
    __syncthreads();
    if (tid < 128) {
        float nm = sqrtf(ssq[tid*2] + ssq[tid*2+1]);
        rsc[tid] = 1.0f / fmaxf(nm, 1e-12f);
    }
    __syncthreads();
    {   // normalize KT
        int d = tid >> 1, zb = (tid & 1) * 64;
#pragma unroll 8
        for (int z2 = 0; z2 < 64; z2++)
            KT[d*132 + zb + z2] *= rsc[zb + z2];
    }
    __syncthreads();

    int tx = tid & 15, ty = tid >> 4;
    int qs = ty*4, kz = tx*8;
    float acc[4][8];
#pragma unroll
    for (int i = 0; i < 4; i++)
#pragma unroll
        for (int j = 0; j < 8; j++) acc[i][j] = 0.f;

#pragma unroll 4
    for (int d = 0; d < 128; d++) {
        float4 k0 = *(const float4*)&KT[d*132 + kz];
        float4 k1 = *(const float4*)&KT[d*132 + kz + 4];
#pragma unroll
        for (int i = 0; i < 4; i++) {
            float q = QT[d*68 + qs + i];
            acc[i][0] += q*k0.x; acc[i][1] += q*k0.y; acc[i][2] += q*k0.z; acc[i][3] += q*k0.w;
            acc[i][4] += q*k1.x; acc[i][5] += q*k1.y; acc[i][6] += q*k1.z; acc[i][7] += q*k1.w;
        }
    }

    int lq[4][8], pq[4], bqr[4];
#pragma unroll
    for (int i = 0; i < 4; i++) {
        pq[i] = posq[qs+i];
        bqr[i] = bqv[qs+i];
#pragma unroll
        for (int hh = 0; hh < 8; hh++) lq[i][hh] = sLq[(qs+i)*8 + hh];
    }
#pragma unroll
    for (int j = 0; j < 8; j++) {
        int z = kz + j;
        int pk = posk[z];
        int bk = bkv[z];
        int lk[8], l2[8];
#pragma unroll
        for (int hh = 0; hh < 8; hh++) {
            int lkv = sLk[z*8 + hh];
            lk[hh] = lkv;
            l2[hh] = (lkv & ~511) | ((lkv + 1) & 511);
        }
#pragma unroll
        for (int i = 0; i < 4; i++) {
            float val = acc[i][j];
            if (bqr[i] != bk)       val = MNEG;
            else if (pq[i] == pk)   val = -10000.0f;
            else if (pq[i] < pk)    val = MNEG;
            int cnt = 0;
#pragma unroll
            for (int hh = 0; hh < 8; hh++)
                cnt += (lq[i][hh] == lk[hh]) + (lq[i][hh] == l2[hh]);
            val -= logf((float)cnt + 1e-9f);
            SP[(qs+i)*132 + z] = val;
        }
    }
    __syncthreads();

    int wid = tid >> 5, lane = tid & 31;
    for (int r8 = 0; r8 < 8; r8++) {
        int r = wid*8 + r8;
        float v0 = SP[r*132 + lane];
        float v1 = SP[r*132 + lane + 32];
        float v2 = SP[r*132 + lane + 64];
        float v3 = SP[r*132 + lane + 96];
        float m = fmaxf(fmaxf(v0, v1), fmaxf(v2, v3));
#pragma unroll
        for (int off = 16; off >= 1; off >>= 1)
            m = fmaxf(m, __shfl_xor_sync(0xffffffffu, m, off));
        float e0 = expf(v0 - m), e1 = expf(v1 - m), e2 = expf(v2 - m), e3 = expf(v3 - m);
        float sum = e0 + e1 + e2 + e3;
#pragma unroll
        for (int off = 16; off >= 1; off >>= 1)
            sum += __shfl_xor_sync(0xffffffffu, sum, off);
        float inv = 1.0f / sum;
        SP[r*132 + lane]      = e0 * inv;
        SP[r*132 + lane + 32] = e1 * inv;
        SP[r*132 + lane + 64] = e2 * inv;
        SP[r*132 + lane + 96] = e3 * inv;
        if (lane == 0)
            g_lse[b*NSLOT + c*CHUNK + r] = m + logf(sum);
    }
    __syncthreads();

    float o[4][8];
#pragma unroll
    for (int i = 0; i < 4; i++)
#pragma unroll
        for (int j = 0; j < 8; j++) o[i][j] = 0.f;

#pragma unroll 4
    for (int z = 0; z < 128; z++) {
        float4 u0 = *(const float4*)&SV[z*132 + kz];
        float4 u1 = *(const float4*)&SV[z*132 + kz + 4];
#pragma unroll
        for (int i = 0; i < 4; i++) {
            float p = SP[(qs+i)*132 + z];
            o[i][0] += p*u0.x; o[i][1] += p*u0.y; o[i][2] += p*u0.z; o[i][3] += p*u0.w;
            o[i][4] += p*u1.x; o[i][5] += p*u1.y; o[i][6] += p*u1.z; o[i][7] += p*u1.w;
        }
    }
#pragma unroll
    for (int i = 0; i < 4; i++) {
        size_t row = ((size_t)b*NSLOT + c*CHUNK + qs + i) * DIM + kz;
        *(float4*)&g_bo[row]     = make_float4(o[i][0], o[i][1], o[i][2], o[i][3]);
        *(float4*)&g_bo[row + 4] = make_float4(o[i][4], o[i][5], o[i][6], o[i][7]);
    }
}

// ---------------- K4: un-sort + combine ----------------
__global__ void k_combine(float* __restrict__ out) {
    int pb = blockIdx.x;              // b*SEQ + pos
    int b  = pb >> 12;
    int tid = threadIdx.x;
    __shared__ int   sslot[8];
    __shared__ float slse[8];
    if (tid < 8) {
        int slot = g_slotof[pb*NHASH + tid];
        sslot[tid] = slot;
        slse[tid]  = g_lse[b*NSLOT + slot];
    }
    __syncthreads();
    float m = slse[0];
#pragma unroll
    for (int h = 1; h < 8; h++) m = fmaxf(m, slse[h]);
    float w[8], wsum = 0.f;
#pragma unroll
    for (int h = 0; h < 8; h++) { w[h] = expf(slse[h] - m); wsum += w[h]; }
    float inv = 1.0f / wsum;
    float acc = 0.f;
#pragma unroll
    for (int h = 0; h < 8; h++)
        acc += w[h] * g_bo[((size_t)b*NSLOT + sslot[h]) * DIM + tid];
    out[(size_t)pb*DIM + tid] = acc * inv;
}

// ---------------- launcher ----------------
extern "C" void kernel_launch(void* const* d_in, const int* in_sizes, int n_in,
                              void* d_out, int out_size) {
    const float* qk  = (const float*)d_in[0];
    const float* v   = (const float*)d_in[1];
    const float* rot = (const float*)d_in[2];
    float* out = (float*)d_out;

    const int HASH_SMEM = (32768 + 4096) * 4;
    const int SCAT_SMEM = 64 * 257 * 4;
    const int ATTN_SMEM = (128*68 + 128*132 + 128*132 + 64*132
                           + 64 + 128 + 64 + 128 + 512 + 1024 + 256 + 128) * 4;

    cudaFuncSetAttribute(k_hash,    cudaFuncAttributeMaxDynamicSharedMemorySize, HASH_SMEM);
    cudaFuncSetAttribute(k_scatter, cudaFuncAttributeMaxDynamicSharedMemorySize, SCAT_SMEM);
    cudaFuncSetAttribute(k_attn,    cudaFuncAttributeMaxDynamicSharedMemorySize, ATTN_SMEM);

    void* cptr = nullptr;
    cudaGetSymbolAddress(&cptr, g_counts);
    cudaMemsetAsync(cptr, 0, sizeof(int) * NBATCH * 512, 0);

    k_hash   <<<(NBATCH*SEQ)/32, 256, HASH_SMEM>>>(qk, rot);
    k_hist   <<<(NBATCH*NHASH*SEQ)/256, 256>>>();
    k_prefix <<<NBATCH, 512>>>();
    k_scatter<<<NBATCH*NHASH, 256, SCAT_SMEM>>>();
    k_attn   <<<NBATCH*NCHUNK, 256, ATTN_SMEM>>>(qk, v);
    k_combine<<<NBATCH*SEQ, 128>>>(out);
}

// round 9
// speedup vs baseline: 1.6190x; 1.6190x over previous
#include <cuda_runtime.h>
#include <cuda_bf16.h>
#include <math.h>
#include <float.h>
#include <stdint.h>

#define NBATCH 8
#define SEQ    4096
#define DIM    128
#define NHASH  8
#define NBUCK  64
#define NCHUNK 512
#define NSLOT  32768
#define CHUNK  64
#define QKSCALE 0.08838834764831843f
#define MNEG   (-3.402823466e38f)

__device__ int   g_buckets[NBATCH*NHASH*SEQ];
__device__ int   g_counts [NBATCH*512];
__device__ int   g_bstart [NBATCH*512];
__device__ int   g_st     [NBATCH*NSLOT];
__device__ int   g_sb     [NBATCH*NSLOT];
__device__ int   g_slotof [NBATCH*SEQ*NHASH];
__device__ int   g_L      [NBATCH*SEQ*NHASH];
__device__ float g_lse    [NBATCH*NSLOT];
__device__ float g_bo     [(size_t)NBATCH*NSLOT*DIM];

// ===================== helpers =====================
__device__ __forceinline__ uint32_t smem_to_u32(const void* p) {
    uint32_t a;
    asm("{ .reg .u64 t; cvta.to.shared.u64 t, %1; cvt.u32.u64 %0, t; }" : "=r"(a) : "l"(p));
    return a;
}
__device__ __forceinline__ uint32_t pack_bf2(float a, float b) {
    __nv_bfloat162 t;
    t.x = __float2bfloat16_rn(a);
    t.y = __float2bfloat16_rn(b);
    return *(uint32_t*)&t;
}
__device__ __forceinline__ void ldsm_x4(uint32_t addr, uint32_t& r0, uint32_t& r1, uint32_t& r2, uint32_t& r3) {
    asm volatile("ldmatrix.sync.aligned.m8n8.x4.shared.b16 {%0,%1,%2,%3}, [%4];"
                 : "=r"(r0), "=r"(r1), "=r"(r2), "=r"(r3) : "r"(addr));
}
__device__ __forceinline__ void ldsm_x2(uint32_t addr, uint32_t& r0, uint32_t& r1) {
    asm volatile("ldmatrix.sync.aligned.m8n8.x2.shared.b16 {%0,%1}, [%2];"
                 : "=r"(r0), "=r"(r1) : "r"(addr));
}
__device__ __forceinline__ void mma16816(float* c, uint32_t a0, uint32_t a1, uint32_t a2, uint32_t a3,
                                         uint32_t b0, uint32_t b1) {
    asm volatile("mma.sync.aligned.m16n8k16.row.col.f32.bf16.bf16.f32 "
                 "{%0,%1,%2,%3}, {%4,%5,%6,%7}, {%8,%9}, {%0,%1,%2,%3};"
                 : "+f"(c[0]), "+f"(c[1]), "+f"(c[2]), "+f"(c[3])
                 : "r"(a0), "r"(a1), "r"(a2), "r"(a3), "r"(b0), "r"(b1));
}

// ===================== K1: LSH hashing =====================
__global__ void k_hash(const float* __restrict__ qk, const float* __restrict__ rot) {
    extern __shared__ float sm[];
    float* srot = sm;
    float* sq   = sm + 32768;
    int tid = threadIdx.x;
    for (int i = tid; i < 32768/4; i += 256)
        ((float4*)srot)[i] = ((const float4*)rot)[i];
    int tok0 = blockIdx.x * 32;
    int b = tok0 >> 12;
    int s0 = tok0 & 4095;
    const float* qbase = qk + (size_t)tok0 * DIM;
    for (int i = tid; i < (32*128)/4; i += 256)
        ((float4*)sq)[i] = ((const float4*)qbase)[i];
    __syncthreads();

    int ngrp = tid & 31, tgrp = tid >> 5;
    int hub = ngrp * 8, tb = tgrp * 4;
    float acc[4][8];
#pragma unroll
    for (int i = 0; i < 4; i++)
#pragma unroll
        for (int j = 0; j < 8; j++) acc[i][j] = 0.f;
#pragma unroll 4
    for (int d = 0; d < 128; d++) {
        float4 r0 = *(const float4*)(srot + d*256 + hub);
        float4 r1 = *(const float4*)(srot + d*256 + hub + 4);
#pragma unroll
        for (int i = 0; i < 4; i++) {
            float q = sq[(tb+i)*128 + d];
            acc[i][0] += q*r0.x; acc[i][1] += q*r0.y; acc[i][2] += q*r0.z; acc[i][3] += q*r0.w;
            acc[i][4] += q*r1.x; acc[i][5] += q*r1.y; acc[i][6] += q*r1.z; acc[i][7] += q*r1.w;
        }
    }
    int h = ngrp >> 2, k = ngrp & 3;
#pragma unroll
    for (int i = 0; i < 4; i++) {
        float bv = -1.0f; int bi = 0;
#pragma unroll
        for (int j = 0; j < 8; j++) {
            float r = acc[i][j];
            float a = fabsf(r);
            int n  = k*8 + j;
            int ci = (r < 0.f) ? (n + 32) : n;
            if (a > bv || (a == bv && ci < bi)) { bv = a; bi = ci; }
        }
#pragma unroll
        for (int off = 1; off <= 2; off <<= 1) {
            float ov = __shfl_xor_sync(0xffffffffu, bv, off);
            int   oi = __shfl_xor_sync(0xffffffffu, bi, off);
            if (ov > bv || (ov == bv && oi < bi)) { bv = ov; bi = oi; }
        }
        if (k == 0)
            g_buckets[((b*NHASH + h) * SEQ) + s0 + tb + i] = h*NBUCK + bi;
    }
}

// ===================== K2: counting sort =====================
__global__ void k_hist() {
    int i = blockIdx.x * 256 + threadIdx.x;
    int b = i >> 15;
    atomicAdd(&g_counts[b*512 + g_buckets[i]], 1);
}
__global__ void k_prefix() {
    __shared__ int sc[512];
    int b = blockIdx.x, t = threadIdx.x;
    int v = g_counts[b*512 + t];
    sc[t] = v;
    __syncthreads();
    for (int off = 1; off < 512; off <<= 1) {
        int add = (t >= off) ? sc[t-off] : 0;
        __syncthreads();
        sc[t] += add;
        __syncthreads();
    }
    g_bstart[b*512 + t] = sc[t] - v;
}
__global__ void k_scatter() {
    extern __shared__ int sh[];
    int b = blockIdx.x >> 3, h = blockIdx.x & 7;
    int t = threadIdx.x;
    const int* bk = &g_buckets[(b*NHASH + h) * SEQ];
    for (int i = t; i < 64*257; i += 256) sh[i] = 0;
    __syncthreads();
    int p0 = t * 16;
#pragma unroll
    for (int q = 0; q < 16; q++) {
        int c = bk[p0 + q] - h*NBUCK;
        sh[c*257 + t]++;
    }
    __syncthreads();
    if (t < 64) {
        int run = g_bstart[b*512 + h*NBUCK + t];
        for (int u = 0; u < 256; u++) {
            int v = sh[t*257 + u];
            sh[t*257 + u] = run;
            run += v;
        }
    }
    __syncthreads();
#pragma unroll
    for (int q = 0; q < 16; q++) {
        int pos = p0 + q;
        int Bg  = bk[pos];
        int c   = Bg - h*NBUCK;
        int slot = sh[c*257 + t]++;
        g_st[b*NSLOT + slot] = pos;
        g_sb[b*NSLOT + slot] = Bg;
        g_slotof[(b*SEQ + pos)*NHASH + h] = slot;
        g_L     [(b*SEQ + pos)*NHASH + h] = Bg*512 + (slot >> 6);
    }
}

// ===================== K3: mma.sync tensor-core attention =====================
// Row stride: 136 bf16 = 272 bytes (17*16B -> stride mod 32 banks = 4; ldmatrix conflict-free)
#define RS 272
#define QH_OFF   0        // 64*272 = 17408
#define QL_OFF   17408    // ends 34816
#define SP_OFF   0        // fp32 [64][132] = 33792, aliases Q region after GEMM1
#define KH_OFF   34816    // 128*272 = 34816
#define KL_OFF   69632    // ends 104448
#define PH_OFF   34816    // aliases KH after GEMM1
#define PL_OFF   52224    // ends 69632 (inside K region)
#define VTH_OFF  104448
#define VTL_OFF  139264   // ends 174080
#define PQB_OFF  174080   // int2[64]
#define POSK_OFF 174592   // int[128]
#define BKV_OFF  175104   // int[128]
#define SLQ_OFF  175616   // int[512]
#define SLK_OFF  177664   // int[1024]
#define SINV_OFF 181760   // float[64]
#define ATTN_SMEM 182272

__global__ __launch_bounds__(256, 1) void k_attn_tc(const float* __restrict__ qk,
                                                    const float* __restrict__ vin) {
    extern __shared__ char smem[];
    uint32_t sb = smem_to_u32(smem);
    int tid = threadIdx.x;
    int w   = tid >> 5, lane = tid & 31;

    int bid = blockIdx.x;
    int b = bid >> 9;
    int c = bid & 511;
    int cprev = (c + NCHUNK - 1) & 511;

    int2*  pqb  = (int2*)(smem + PQB_OFF);
    int*   posk = (int*)(smem + POSK_OFF);
    int*   bkv  = (int*)(smem + BKV_OFF);
    int*   sLq  = (int*)(smem + SLQ_OFF);
    int*   sLk  = (int*)(smem + SLK_OFF);
    float* sinv = (float*)(smem + SINV_OFF);
    float* SPf  = (float*)(smem + SP_OFF);

    // ---- metadata gather ----
    if (tid < 64) {
        int slot = c*CHUNK + tid;
        int pos  = g_st[b*NSLOT + slot];
        pqb[tid] = make_int2(pos, g_sb[b*NSLOT + slot]);
        const int4* lp = (const int4*)&g_L[(b*SEQ + pos)*NHASH];
        ((int4*)(sLq + tid*8))[0] = lp[0];
        ((int4*)(sLq + tid*8))[1] = lp[1];
    } else if (tid < 192) {
        int z = tid - 64;
        int slot = (z < 64) ? (c*CHUNK + z) : (cprev*CHUNK + (z - 64));
        int pos  = g_st[b*NSLOT + slot];
        posk[z] = pos;
        bkv[z]  = g_sb[b*NSLOT + slot];
        const int4* lp = (const int4*)&g_L[(b*SEQ + pos)*NHASH];
        ((int4*)(sLk + z*8))[0] = lp[0];
        ((int4*)(sLk + z*8))[1] = lp[1];
    }
    __syncthreads();

    // ---- stage Q (hi/lo), rows [64][136], k=d contiguous ----
    {
        int q = tid >> 2, part = tid & 3;
        const float* src = qk + ((size_t)b*SEQ + pqb[q].x)*DIM + part*32;
        char* dstH = smem + QH_OFF + q*RS + part*64;
        char* dstL = smem + QL_OFF + q*RS + part*64;
#pragma unroll
        for (int c8 = 0; c8 < 4; c8++) {
            float4 a = ((const float4*)src)[c8*2];
            float4 d = ((const float4*)src)[c8*2 + 1];
            float f[8] = {a.x,a.y,a.z,a.w,d.x,d.y,d.z,d.w};
            uint32_t hi[4], lo[4];
#pragma unroll
            for (int e = 0; e < 4; e++) {
                float v0 = f[e*2]   * QKSCALE;
                float v1 = f[e*2+1] * QKSCALE;
                __nv_bfloat16 h0 = __float2bfloat16_rn(v0);
                __nv_bfloat16 h1 = __float2bfloat16_rn(v1);
                __nv_bfloat162 hh; hh.x = h0; hh.y = h1; hi[e] = *(uint32_t*)&hh;
                lo[e] = pack_bf2(v0 - __bfloat162float(h0), v1 - __bfloat162float(h1));
            }
            *(uint4*)(dstH + c8*16) = make_uint4(hi[0],hi[1],hi[2],hi[3]);
            *(uint4*)(dstL + c8*16) = make_uint4(lo[0],lo[1],lo[2],lo[3]);
        }
    }
    // ---- stage K (normalized, hi/lo), rows [128][136] ----
    {
        int z = tid >> 1, half = tid & 1;
        const float* src = qk + ((size_t)b*SEQ + posk[z])*DIM + half*64;
        float ss = 0.f;
#pragma unroll
        for (int k4 = 0; k4 < 16; k4++) {
            float4 kv = ((const float4*)src)[k4];
            ss += kv.x*kv.x + kv.y*kv.y + kv.z*kv.z + kv.w*kv.w;
        }
        ss += __shfl_xor_sync(0xffffffffu, ss, 1);
        float rscv = 1.0f / fmaxf(sqrtf(ss), 1e-12f);
        char* dstH = smem + KH_OFF + z*RS + half*128;
        char* dstL = smem + KL_OFF + z*RS + half*128;
#pragma unroll
        for (int c8 = 0; c8 < 8; c8++) {
            float4 a = ((const float4*)src)[c8*2];
            float4 d = ((const float4*)src)[c8*2 + 1];
            float f[8] = {a.x,a.y,a.z,a.w,d.x,d.y,d.z,d.w};
            uint32_t hi[4], lo[4];
#pragma unroll
            for (int e = 0; e < 4; e++) {
                float v0 = f[e*2]   * rscv;
                float v1 = f[e*2+1] * rscv;
                __nv_bfloat16 h0 = __float2bfloat16_rn(v0);
                __nv_bfloat16 h1 = __float2bfloat16_rn(v1);
                __nv_bfloat162 hh; hh.x = h0; hh.y = h1; hi[e] = *(uint32_t*)&hh;
                lo[e] = pack_bf2(v0 - __bfloat162float(h0), v1 - __bfloat162float(h1));
            }
            *(uint4*)(dstH + c8*16) = make_uint4(hi[0],hi[1],hi[2],hi[3]);
            *(uint4*)(dstL + c8*16) = make_uint4(lo[0],lo[1],lo[2],lo[3]);
        }
    }
    // ---- stage V^T (hi/lo), rows = d [128][136], k=z contiguous ----
    {
        int z = tid >> 1, half = tid & 1;
        const float* src = vin + ((size_t)b*SEQ + posk[z])*DIM + half*64;
#pragma unroll
        for (int k4 = 0; k4 < 16; k4++) {
            float4 vv = ((const float4*)src)[k4];
            float f[4] = {vv.x, vv.y, vv.z, vv.w};
#pragma unroll
            for (int e = 0; e < 4; e++) {
                int d = half*64 + k4*4 + e;
                __nv_bfloat16 h = __float2bfloat16_rn(f[e]);
                __nv_bfloat16 l = __float2bfloat16_rn(f[e] - __bfloat162float(h));
                *(__nv_bfloat16*)(smem + VTH_OFF + d*RS + z*2) = h;
                *(__nv_bfloat16*)(smem + VTL_OFF + d*RS + z*2) = l;
            }
        }
    }
    __syncthreads();

    // warp tile: q0 = (w&3)*16 rows, zbase = (w>>2)*64 cols
    int q0 = (w & 3) << 4;
    int zbase = (w >> 2) << 6;

    // ldmatrix lane address offsets
    int gA = lane >> 3, iA = lane & 7;
    int arow = iA + (gA & 1)*8;
    int akoff = (gA >> 1)*8;                       // elems
    uint32_t aoffH = sb + QH_OFF + (q0+arow)*RS + akoff*2;
    uint32_t aoffL = sb + QL_OFF + (q0+arow)*RS + akoff*2;
    int brow = lane & 7;
    int bkoff = ((lane >> 3) & 1) * 8;
    uint32_t boffH = sb + KH_OFF + (zbase+brow)*RS + bkoff*2;
    uint32_t boffL = sb + KL_OFF + (zbase+brow)*RS + bkoff*2;

    float acc[8][4];
#pragma unroll
    for (int nt = 0; nt < 8; nt++)
#pragma unroll
        for (int e = 0; e < 4; e++) acc[nt][e] = 0.f;

    // ---- GEMM1: dots[64q x 128z] = Q . K^T  (3-term hi/lo) ----
#pragma unroll
    for (int ks = 0; ks < 8; ks++) {
        uint32_t aH0,aH1,aH2,aH3, aL0,aL1,aL2,aL3;
        ldsm_x4(aoffH + ks*32, aH0,aH1,aH2,aH3);
        ldsm_x4(aoffL + ks*32, aL0,aL1,aL2,aL3);
#pragma unroll
        for (int nt = 0; nt < 8; nt++) {
            uint32_t bH0,bH1,bL0,bL1;
            ldsm_x2(boffH + nt*(8*RS) + ks*32, bH0,bH1);
            ldsm_x2(boffL + nt*(8*RS) + ks*32, bL0,bL1);
            mma16816(acc[nt], aH0,aH1,aH2,aH3, bH0,bH1);
            mma16816(acc[nt], aH0,aH1,aH2,aH3, bL0,bL1);
            mma16816(acc[nt], aL0,aL1,aL2,aL3, bH0,bH1);
        }
    }
    __syncthreads();   // Q region dead -> SP may be written

    // ---- E1: masks + dup-count on register accumulators; write SP[q][z] ----
    {
        int ra = q0 + (lane >> 2);
        int rb = ra + 8;
        int2 pba = pqb[ra], pbb = pqb[rb];
        int lqa[8], lqb[8];
#pragma unroll
        for (int h = 0; h < 8; h++) { lqa[h] = sLq[ra*8 + h]; lqb[h] = sLq[rb*8 + h]; }
#pragma unroll
        for (int nt = 0; nt < 8; nt++) {
#pragma unroll
            for (int cc = 0; cc < 2; cc++) {
                int z = zbase + nt*8 + ((lane & 3) << 1) + cc;
                int pk = posk[z];
                int bk2 = bkv[z];
                int cnta = 0, cntb = 0;
#pragma unroll
                for (int h = 0; h < 8; h++) {
                    int lkv = sLk[z*8 + h];
                    int l2  = (lkv & ~511) | ((lkv + 1) & 511);
                    cnta += (lqa[h] == lkv) + (lqa[h] == l2);
                    cntb += (lqb[h] == lkv) + (lqb[h] == l2);
                }
                float va = acc[nt][cc];
                if (pba.y != bk2)      va = MNEG;
                else if (pba.x == pk)  va = -10000.0f;
                else if (pba.x < pk)   va = MNEG;
                if (cnta > 1) va -= __logf((float)cnta);
                float vb = acc[nt][2 + cc];
                if (pbb.y != bk2)      vb = MNEG;
                else if (pbb.x == pk)  vb = -10000.0f;
                else if (pbb.x < pk)   vb = MNEG;
                if (cntb > 1) vb -= __logf((float)cntb);
                SPf[ra*132 + z] = va;
                SPf[rb*132 + z] = vb;
            }
        }
    }
    __syncthreads();

    // ---- E2: softmax per query row (unnormalized exp in SP, sinv + lse out) ----
    {
#pragma unroll
        for (int rr = 0; rr < 8; rr++) {
            int q = w*8 + rr;
            float4 vv = *(float4*)&SPf[q*132 + lane*4];
            float m = fmaxf(fmaxf(vv.x, vv.y), fmaxf(vv.z, vv.w));
#pragma unroll
            for (int off = 16; off >= 1; off >>= 1)
                m = fmaxf(m, __shfl_xor_sync(0xffffffffu, m, off));
            float4 e;
            e.x = __expf(vv.x - m); e.y = __expf(vv.y - m);
            e.z = __expf(vv.z - m); e.w = __expf(vv.w - m);
            float s = e.x + e.y + e.z + e.w;
#pragma unroll
            for (int off = 16; off >= 1; off >>= 1)
                s += __shfl_xor_sync(0xffffffffu, s, off);
            *(float4*)&SPf[q*132 + lane*4] = e;
            if (lane == 0) {
                sinv[q] = 1.0f / s;
                g_lse[b*NSLOT + c*CHUNK + q] = m + __logf(s);
            }
        }
    }
    __syncthreads();

    // ---- E3: pack P hi/lo into [64][136] rows (aliases dead K region) ----
    {
        int q = tid >> 2, part = tid & 3;
        char* dstH = smem + PH_OFF + q*RS + part*64;
        char* dstL = smem + PL_OFF + q*RS + part*64;
#pragma unroll
        for (int c8 = 0; c8 < 4; c8++) {
            int z0 = part*32 + c8*8;
            float4 a = *(float4*)&SPf[q*132 + z0];
            float4 d = *(float4*)&SPf[q*132 + z0 + 4];
            float f[8] = {a.x,a.y,a.z,a.w,d.x,d.y,d.z,d.w};
            uint32_t hi[4], lo[4];
#pragma unroll
            for (int e = 0; e < 4; e++) {
                __nv_bfloat16 h0 = __float2bfloat16_rn(f[e*2]);
                __nv_bfloat16 h1 = __float2bfloat16_rn(f[e*2+1]);
                __nv_bfloat162 hh; hh.x = h0; hh.y = h1; hi[e] = *(uint32_t*)&hh;
                lo[e] = pack_bf2(f[e*2] - __bfloat162float(h0), f[e*2+1] - __bfloat162float(h1));
            }
            *(uint4*)(dstH + c8*16) = make_uint4(hi[0],hi[1],hi[2],hi[3]);
            *(uint4*)(dstL + c8*16) = make_uint4(lo[0],lo[1],lo[2],lo[3]);
        }
    }
    __syncthreads();

    // ---- GEMM2: O[64q x 128d] = P . V^T  (3-term hi/lo) ----
#pragma unroll
    for (int nt = 0; nt < 8; nt++)
#pragma unroll
        for (int e = 0; e < 4; e++) acc[nt][e] = 0.f;
    {
        uint32_t paH = sb + PH_OFF + (q0+arow)*RS + akoff*2;
        uint32_t paL = sb + PL_OFF + (q0+arow)*RS + akoff*2;
        uint32_t vbH = sb + VTH_OFF + (zbase+brow)*RS + bkoff*2;  // zbase doubles as dbase
        uint32_t vbL = sb + VTL_OFF + (zbase+brow)*RS + bkoff*2;
#pragma unroll
        for (int ks = 0; ks < 8; ks++) {
            uint32_t aH0,aH1,aH2,aH3, aL0,aL1,aL2,aL3;
            ldsm_x4(paH + ks*32, aH0,aH1,aH2,aH3);
            ldsm_x4(paL + ks*32, aL0,aL1,aL2,aL3);
#pragma unroll
            for (int nt = 0; nt < 8; nt++) {
                uint32_t bH0,bH1,bL0,bL1;
                ldsm_x2(vbH + nt*(8*RS) + ks*32, bH0,bH1);
                ldsm_x2(vbL + nt*(8*RS) + ks*32, bL0,bL1);
                mma16816(acc[nt], aH0,aH1,aH2,aH3, bH0,bH1);
                mma16816(acc[nt], aH0,aH1,aH2,aH3, bL0,bL1);
                mma16816(acc[nt], aL0,aL1,aL2,aL3, bH0,bH1);
            }
        }
    }
    __syncthreads();   // SP (exp values) fully consumed -> reuse for O staging

    // ---- stage O into SP[q][d] with sinv scaling ----
    {
        int ra = q0 + (lane >> 2);
        int rb = ra + 8;
        float sa = sinv[ra], sbv = sinv[rb];
#pragma unroll
        for (int nt = 0; nt < 8; nt++) {
            int d = zbase + nt*8 + ((lane & 3) << 1);
            *(float2*)&SPf[ra*132 + d] = make_float2(acc[nt][0]*sa, acc[nt][1]*sa);
            *(float2*)&SPf[rb*132 + d] = make_float2(acc[nt][2]*sbv, acc[nt][3]*sbv);
        }
    }
    __syncthreads();

    // ---- coalesced write to g_bo ----
    {
        int q = tid >> 2, part = tid & 3;
        float* dst = &g_bo[((size_t)b*NSLOT + c*CHUNK + q)*DIM + part*32];
#pragma unroll
        for (int i = 0; i < 8; i++)
            ((float4*)dst)[i] = *(float4*)&SPf[q*132 + part*32 + i*4];
    }
}

// ===================== K4: un-sort + combine =====================
__global__ void k_combine(float* __restrict__ out) {
    int pb = blockIdx.x;
    int b  = pb >> 12;
    int tid = threadIdx.x;
    __shared__ int   sslot[8];
    __shared__ float slse[8];
    if (tid < 8) {
        int slot = g_slotof[pb*NHASH + tid];
        sslot[tid] = slot;
        slse[tid]  = g_lse[b*NSLOT + slot];
    }
    __syncthreads();
    float m = slse[0];
#pragma unroll
    for (int h = 1; h < 8; h++) m = fmaxf(m, slse[h]);
    float w[8], wsum = 0.f;
#pragma unroll
    for (int h = 0; h < 8; h++) { w[h] = __expf(slse[h] - m); wsum += w[h]; }
    float inv = 1.0f / wsum;
    float acc = 0.f;
#pragma unroll
    for (int h = 0; h < 8; h++)
        acc += w[h] * g_bo[((size_t)b*NSLOT + sslot[h]) * DIM + tid];
    out[(size_t)pb*DIM + tid] = acc * inv;
}

// ===================== launcher =====================
extern "C" void kernel_launch(void* const* d_in, const int* in_sizes, int n_in,
                              void* d_out, int out_size) {
    const float* qk  = (const float*)d_in[0];
    const float* v   = (const float*)d_in[1];
    const float* rot = (const float*)d_in[2];
    float* out = (float*)d_out;

    const int HASH_SMEM = (32768 + 4096) * 4;
    const int SCAT_SMEM = 64 * 257 * 4;

    cudaFuncSetAttribute(k_hash,    cudaFuncAttributeMaxDynamicSharedMemorySize, HASH_SMEM);
    cudaFuncSetAttribute(k_scatter, cudaFuncAttributeMaxDynamicSharedMemorySize, SCAT_SMEM);
    cudaFuncSetAttribute(k_attn_tc, cudaFuncAttributeMaxDynamicSharedMemorySize, ATTN_SMEM);

    void* cptr = nullptr;
    cudaGetSymbolAddress(&cptr, g_counts);
    cudaMemsetAsync(cptr, 0, sizeof(int) * NBATCH * 512, 0);

    k_hash   <<<(NBATCH*SEQ)/32, 256, HASH_SMEM>>>(qk, rot);
    k_hist   <<<(NBATCH*NHASH*SEQ)/256, 256>>>();
    k_prefix <<<NBATCH, 512>>>();
    k_scatter<<<NBATCH*NHASH, 256, SCAT_SMEM>>>();
    k_attn_tc<<<NBATCH*NCHUNK, 256, ATTN_SMEM>>>(qk, v);
    k_combine<<<NBATCH*SEQ, 128>>>(out);
}

// round 12
// speedup vs baseline: 1.6275x; 1.0052x over previous
#include <cuda_runtime.h>
#include <cuda_bf16.h>
#include <math.h>
#include <float.h>
#include <stdint.h>

#define NBATCH 8
#define SEQ    4096
#define DIM    128
#define NHASH  8
#define NBUCK  64
#define NCHUNK 512
#define NSLOT  32768
#define CHUNK  64
#define QKSCALE 0.08838834764831843f
#define MNEG   (-3.402823466e38f)

__device__ int   g_buckets[NBATCH*NHASH*SEQ];
__device__ int   g_counts [NBATCH*512];
__device__ int   g_bstart [NBATCH*512];
__device__ int   g_st     [NBATCH*NSLOT];
__device__ int   g_sb     [NBATCH*NSLOT];
__device__ int   g_slotof [NBATCH*SEQ*NHASH];
__device__ int   g_L      [NBATCH*SEQ*NHASH];
__device__ float g_lse    [NBATCH*NSLOT];
__device__ float g_bo     [(size_t)NBATCH*NSLOT*DIM];

// ===================== helpers =====================
__device__ __forceinline__ uint32_t smem_to_u32(const void* p) {
    uint32_t a;
    asm("{ .reg .u64 t; cvta.to.shared.u64 t, %1; cvt.u32.u64 %0, t; }" : "=r"(a) : "l"(p));
    return a;
}
__device__ __forceinline__ uint32_t pack_bf2(float a, float b) {
    __nv_bfloat162 t;
    t.x = __float2bfloat16_rn(a);
    t.y = __float2bfloat16_rn(b);
    return *(uint32_t*)&t;
}
__device__ __forceinline__ void ldsm_x4(uint32_t addr, uint32_t& r0, uint32_t& r1, uint32_t& r2, uint32_t& r3) {
    asm volatile("ldmatrix.sync.aligned.m8n8.x4.shared.b16 {%0,%1,%2,%3}, [%4];"
                 : "=r"(r0), "=r"(r1), "=r"(r2), "=r"(r3) : "r"(addr));
}
__device__ __forceinline__ void ldsm_x4_t(uint32_t addr, uint32_t& r0, uint32_t& r1, uint32_t& r2, uint32_t& r3) {
    asm volatile("ldmatrix.sync.aligned.m8n8.x4.trans.shared.b16 {%0,%1,%2,%3}, [%4];"
                 : "=r"(r0), "=r"(r1), "=r"(r2), "=r"(r3) : "r"(addr));
}
__device__ __forceinline__ void mma16816(float* c, uint32_t a0, uint32_t a1, uint32_t a2, uint32_t a3,
                                         uint32_t b0, uint32_t b1) {
    asm volatile("mma.sync.aligned.m16n8k16.row.col.f32.bf16.bf16.f32 "
                 "{%0,%1,%2,%3}, {%4,%5,%6,%7}, {%8,%9}, {%0,%1,%2,%3};"
                 : "+f"(c[0]), "+f"(c[1]), "+f"(c[2]), "+f"(c[3])
                 : "r"(a0), "r"(a1), "r"(a2), "r"(a3), "r"(b0), "r"(b1));
}

// ===================== K1: LSH hashing =====================
__global__ void k_hash(const float* __restrict__ qk, const float* __restrict__ rot) {
    extern __shared__ float sm[];
    float* srot = sm;
    float* sq   = sm + 32768;
    int tid = threadIdx.x;
    for (int i = tid; i < 32768/4; i += 256)
        ((float4*)srot)[i] = ((const float4*)rot)[i];
    int tok0 = blockIdx.x * 32;
    int b = tok0 >> 12;
    int s0 = tok0 & 4095;
    const float* qbase = qk + (size_t)tok0 * DIM;
    for (int i = tid; i < (32*128)/4; i += 256)
        ((float4*)sq)[i] = ((const float4*)qbase)[i];
    __syncthreads();

    int ngrp = tid & 31, tgrp = tid >> 5;
    int hub = ngrp * 8, tb = tgrp * 4;
    float acc[4][8];
#pragma unroll
    for (int i = 0; i < 4; i++)
#pragma unroll
        for (int j = 0; j < 8; j++) acc[i][j] = 0.f;
#pragma unroll 4
    for (int d = 0; d < 128; d++) {
        float4 r0 = *(const float4*)(srot + d*256 + hub);
        float4 r1 = *(const float4*)(srot + d*256 + hub + 4);
#pragma unroll
        for (int i = 0; i < 4; i++) {
            float q = sq[(tb+i)*128 + d];
            acc[i][0] += q*r0.x; acc[i][1] += q*r0.y; acc[i][2] += q*r0.z; acc[i][3] += q*r0.w;
            acc[i][4] += q*r1.x; acc[i][5] += q*r1.y; acc[i][6] += q*r1.z; acc[i][7] += q*r1.w;
        }
    }
    int h = ngrp >> 2, k = ngrp & 3;
#pragma unroll
    for (int i = 0; i < 4; i++) {
        float bv = -1.0f; int bi = 0;
#pragma unroll
        for (int j = 0; j < 8; j++) {
            float r = acc[i][j];
            float a = fabsf(r);
            int n  = k*8 + j;
            int ci = (r < 0.f) ? (n + 32) : n;
            if (a > bv || (a == bv && ci < bi)) { bv = a; bi = ci; }
        }
#pragma unroll
        for (int off = 1; off <= 2; off <<= 1) {
            float ov = __shfl_xor_sync(0xffffffffu, bv, off);
            int   oi = __shfl_xor_sync(0xffffffffu, bi, off);
            if (ov > bv || (ov == bv && oi < bi)) { bv = ov; bi = oi; }
        }
        if (k == 0)
            g_buckets[((b*NHASH + h) * SEQ) + s0 + tb + i] = h*NBUCK + bi;
    }
}

// ===================== K2: counting sort =====================
__global__ void k_hist() {
    int i = blockIdx.x * 256 + threadIdx.x;
    int b = i >> 15;
    atomicAdd(&g_counts[b*512 + g_buckets[i]], 1);
}
__global__ void k_prefix() {
    __shared__ int sc[512];
    int b = blockIdx.x, t = threadIdx.x;
    int v = g_counts[b*512 + t];
    sc[t] = v;
    __syncthreads();
    for (int off = 1; off < 512; off <<= 1) {
        int add = (t >= off) ? sc[t-off] : 0;
        __syncthreads();
        sc[t] += add;
        __syncthreads();
    }
    g_bstart[b*512 + t] = sc[t] - v;
}
__global__ void k_scatter() {
    extern __shared__ int sh[];
    int b = blockIdx.x >> 3, h = blockIdx.x & 7;
    int t = threadIdx.x;
    const int* bk = &g_buckets[(b*NHASH + h) * SEQ];
    for (int i = t; i < 64*257; i += 256) sh[i] = 0;
    __syncthreads();
    int p0 = t * 16;
#pragma unroll
    for (int q = 0; q < 16; q++) {
        int c = bk[p0 + q] - h*NBUCK;
        sh[c*257 + t]++;
    }
    __syncthreads();
    if (t < 64) {
        int run = g_bstart[b*512 + h*NBUCK + t];
        for (int u = 0; u < 256; u++) {
            int v = sh[t*257 + u];
            sh[t*257 + u] = run;
            run += v;
        }
    }
    __syncthreads();
#pragma unroll
    for (int q = 0; q < 16; q++) {
        int pos = p0 + q;
        int Bg  = bk[pos];
        int c   = Bg - h*NBUCK;
        int slot = sh[c*257 + t]++;
        g_st[b*NSLOT + slot] = pos;
        g_sb[b*NSLOT + slot] = Bg;
        g_slotof[(b*SEQ + pos)*NHASH + h] = slot;
        g_L     [(b*SEQ + pos)*NHASH + h] = Bg*512 + (slot >> 6);
    }
}

// ===================== K3: mma.sync tensor-core attention =====================
// Row stride: 136 bf16 = 272 bytes (17*16B -> stride mod 32 banks = 4; ldmatrix conflict-free)
#define RS 272
#define QH_OFF   0        // 64*272 = 17408
#define QL_OFF   17408    // ends 34816
#define SP_OFF   0        // fp32 [64][132] = 33792, aliases Q region after GEMM1
#define KH_OFF   34816    // 128*272 = 34816
#define KL_OFF   69632    // ends 104448
#define PH_OFF   34816    // aliases KH after GEMM1
#define PL_OFF   52224    // ends 69632 (inside K region)
#define VH_OFF   104448   // V row-major [z=128][d=136]
#define VL_OFF   139264   // ends 174080
#define PQB_OFF  174080   // int2[64]
#define POSK_OFF 174592   // int[128]
#define BKV_OFF  175104   // int[128]
#define SLQ_OFF  175616   // int[512]
#define SLK_OFF  177664   // int[1024]
#define SINV_OFF 181760   // float[64]
#define ATTN_SMEM 182272

__global__ __launch_bounds__(256, 1) void k_attn_tc(const float* __restrict__ qk,
                                                    const float* __restrict__ vin) {
    extern __shared__ char smem[];
    uint32_t sb = smem_to_u32(smem);
    int tid = threadIdx.x;
    int w   = tid >> 5, lane = tid & 31;

    int bid = blockIdx.x;
    int b = bid >> 9;
    int c = bid & 511;
    int cprev = (c + NCHUNK - 1) & 511;

    int2*  pqb  = (int2*)(smem + PQB_OFF);
    int*   posk = (int*)(smem + POSK_OFF);
    int*   bkv  = (int*)(smem + BKV_OFF);
    int*   sLq  = (int*)(smem + SLQ_OFF);
    int*   sLk  = (int*)(smem + SLK_OFF);
    float* sinv = (float*)(smem + SINV_OFF);
    float* SPf  = (float*)(smem + SP_OFF);

    // ---- metadata gather ----
    if (tid < 64) {
        int slot = c*CHUNK + tid;
        int pos  = g_st[b*NSLOT + slot];
        pqb[tid] = make_int2(pos, g_sb[b*NSLOT + slot]);
        const int4* lp = (const int4*)&g_L[(b*SEQ + pos)*NHASH];
        ((int4*)(sLq + tid*8))[0] = lp[0];
        ((int4*)(sLq + tid*8))[1] = lp[1];
    } else if (tid < 192) {
        int z = tid - 64;
        int slot = (z < 64) ? (c*CHUNK + z) : (cprev*CHUNK + (z - 64));
        int pos  = g_st[b*NSLOT + slot];
        posk[z] = pos;
        bkv[z]  = g_sb[b*NSLOT + slot];
        const int4* lp = (const int4*)&g_L[(b*SEQ + pos)*NHASH];
        ((int4*)(sLk + z*8))[0] = lp[0];
        ((int4*)(sLk + z*8))[1] = lp[1];
    }
    __syncthreads();

    // ---- stage Q (hi/lo), rows [64][136], k=d contiguous ----
    {
        int q = tid >> 2, part = tid & 3;
        const float* src = qk + ((size_t)b*SEQ + pqb[q].x)*DIM + part*32;
        char* dstH = smem + QH_OFF + q*RS + part*64;
        char* dstL = smem + QL_OFF + q*RS + part*64;
#pragma unroll
        for (int c8 = 0; c8 < 4; c8++) {
            float4 a = ((const float4*)src)[c8*2];
            float4 d = ((const float4*)src)[c8*2 + 1];
            float f[8] = {a.x,a.y,a.z,a.w,d.x,d.y,d.z,d.w};
            uint32_t hi[4], lo[4];
#pragma unroll
            for (int e = 0; e < 4; e++) {
                float v0 = f[e*2]   * QKSCALE;
                float v1 = f[e*2+1] * QKSCALE;
                __nv_bfloat16 h0 = __float2bfloat16_rn(v0);
                __nv_bfloat16 h1 = __float2bfloat16_rn(v1);
                __nv_bfloat162 hh; hh.x = h0; hh.y = h1; hi[e] = *(uint32_t*)&hh;
                lo[e] = pack_bf2(v0 - __bfloat162float(h0), v1 - __bfloat162float(h1));
            }
            *(uint4*)(dstH + c8*16) = make_uint4(hi[0],hi[1],hi[2],hi[3]);
            *(uint4*)(dstL + c8*16) = make_uint4(lo[0],lo[1],lo[2],lo[3]);
        }
    }
    // ---- stage K (normalized, hi/lo), rows [128][136] ----
    {
        int z = tid >> 1, half = tid & 1;
        const float* src = qk + ((size_t)b*SEQ + posk[z])*DIM + half*64;
        float ss = 0.f;
#pragma unroll
        for (int k4 = 0; k4 < 16; k4++) {
            float4 kv = ((const float4*)src)[k4];
            ss += kv.x*kv.x + kv.y*kv.y + kv.z*kv.z + kv.w*kv.w;
        }
        ss += __shfl_xor_sync(0xffffffffu, ss, 1);
        float rscv = 1.0f / fmaxf(sqrtf(ss), 1e-12f);
        char* dstH = smem + KH_OFF + z*RS + half*128;
        char* dstL = smem + KL_OFF + z*RS + half*128;
#pragma unroll
        for (int c8 = 0; c8 < 8; c8++) {
            float4 a = ((const float4*)src)[c8*2];
            float4 d = ((const float4*)src)[c8*2 + 1];
            float f[8] = {a.x,a.y,a.z,a.w,d.x,d.y,d.z,d.w};
            uint32_t hi[4], lo[4];
#pragma unroll
            for (int e = 0; e < 4; e++) {
                float v0 = f[e*2]   * rscv;
                float v1 = f[e*2+1] * rscv;
                __nv_bfloat16 h0 = __float2bfloat16_rn(v0);
                __nv_bfloat16 h1 = __float2bfloat16_rn(v1);
                __nv_bfloat162 hh; hh.x = h0; hh.y = h1; hi[e] = *(uint32_t*)&hh;
                lo[e] = pack_bf2(v0 - __bfloat162float(h0), v1 - __bfloat162float(h1));
            }
            *(uint4*)(dstH + c8*16) = make_uint4(hi[0],hi[1],hi[2],hi[3]);
            *(uint4*)(dstL + c8*16) = make_uint4(lo[0],lo[1],lo[2],lo[3]);
        }
    }
    // ---- stage V row-major (hi/lo), rows [z=128][d=136] (vectorized) ----
    {
        int z = tid >> 1, half = tid & 1;
        const float* src = vin + ((size_t)b*SEQ + posk[z])*DIM + half*64;
        char* dstH = smem + VH_OFF + z*RS + half*128;
        char* dstL = smem + VL_OFF + z*RS + half*128;
#pragma unroll
        for (int c8 = 0; c8 < 8; c8++) {
            float4 a = ((const float4*)src)[c8*2];
            float4 d = ((const float4*)src)[c8*2 + 1];
            float f[8] = {a.x,a.y,a.z,a.w,d.x,d.y,d.z,d.w};
            uint32_t hi[4], lo[4];
#pragma unroll
            for (int e = 0; e < 4; e++) {
                float v0 = f[e*2];
                float v1 = f[e*2+1];
                __nv_bfloat16 h0 = __float2bfloat16_rn(v0);
                __nv_bfloat16 h1 = __float2bfloat16_rn(v1);
                __nv_bfloat162 hh; hh.x = h0; hh.y = h1; hi[e] = *(uint32_t*)&hh;
                lo[e] = pack_bf2(v0 - __bfloat162float(h0), v1 - __bfloat162float(h1));
            }
            *(uint4*)(dstH + c8*16) = make_uint4(hi[0],hi[1],hi[2],hi[3]);
            *(uint4*)(dstL + c8*16) = make_uint4(lo[0],lo[1],lo[2],lo[3]);
        }
    }
    __syncthreads();

    // warp tile: q0 = (w&3)*16 rows, zbase = (w>>2)*64 cols
    int q0 = (w & 3) << 4;
    int zbase = (w >> 2) << 6;

    // A-fragment ldmatrix lane addressing (x4, non-trans)
    int arow  = (lane & 7) + ((lane >> 3) & 1) * 8;
    int akoff = (lane >> 4) * 8;                       // elems
    uint32_t aoffH = sb + QH_OFF + (q0+arow)*RS + akoff*2;
    uint32_t aoffL = sb + QL_OFF + (q0+arow)*RS + akoff*2;
    // B-fragment (GEMM1, x4 non-trans; covers 2 n-tiles): rows via bit4, k-half via bit3
    int brow = (lane & 7) + (lane >> 4) * 8;
    int bk   = ((lane >> 3) & 1) * 8;
    uint32_t boffH = sb + KH_OFF + (zbase + brow)*RS + bk*2;
    uint32_t boffL = sb + KL_OFF + (zbase + brow)*RS + bk*2;

    float acc[8][4];
#pragma unroll
    for (int nt = 0; nt < 8; nt++)
#pragma unroll
        for (int e = 0; e < 4; e++) acc[nt][e] = 0.f;

    // ---- GEMM1: dots[64q x 128z] = Q . K^T  (3-term hi/lo) ----
#pragma unroll
    for (int ks = 0; ks < 8; ks++) {
        uint32_t aH0,aH1,aH2,aH3, aL0,aL1,aL2,aL3;
        ldsm_x4(aoffH + ks*32, aH0,aH1,aH2,aH3);
        ldsm_x4(aoffL + ks*32, aL0,aL1,aL2,aL3);
#pragma unroll
        for (int p = 0; p < 4; p++) {
            uint32_t bH0,bH1,bH2,bH3, bL0,bL1,bL2,bL3;
            ldsm_x4(boffH + p*(16*RS) + ks*32, bH0,bH1,bH2,bH3);
            ldsm_x4(boffL + p*(16*RS) + ks*32, bL0,bL1,bL2,bL3);
            mma16816(acc[2*p],   aH0,aH1,aH2,aH3, bH0,bH1);
            mma16816(acc[2*p],   aH0,aH1,aH2,aH3, bL0,bL1);
            mma16816(acc[2*p],   aL0,aL1,aL2,aL3, bH0,bH1);
            mma16816(acc[2*p+1], aH0,aH1,aH2,aH3, bH2,bH3);
            mma16816(acc[2*p+1], aH0,aH1,aH2,aH3, bL2,bL3);
            mma16816(acc[2*p+1], aL0,aL1,aL2,aL3, bH2,bH3);
        }
    }
    __syncthreads();   // Q region dead -> SP may be written

    // ---- E1: masks + dup-count on register accumulators; write SP[q][z] ----
    {
        int ra = q0 + (lane >> 2);
        int rb = ra + 8;
        int2 pba = pqb[ra], pbb = pqb[rb];
        int lqa[8], lqb[8];
#pragma unroll
        for (int h = 0; h < 8; h++) { lqa[h] = sLq[ra*8 + h]; lqb[h] = sLq[rb*8 + h]; }
#pragma unroll
        for (int nt = 0; nt < 8; nt++) {
#pragma unroll
            for (int cc = 0; cc < 2; cc++) {
                int z = zbase + nt*8 + ((lane & 3) << 1) + cc;
                int pk = posk[z];
                int bk2 = bkv[z];
                int cnta = 0, cntb = 0;
#pragma unroll
                for (int h = 0; h < 8; h++) {
                    int lkv = sLk[z*8 + h];
                    int l2  = (lkv & ~511) | ((lkv + 1) & 511);
                    cnta += (lqa[h] == lkv) + (lqa[h] == l2);
                    cntb += (lqb[h] == lkv) + (lqb[h] == l2);
                }
                float va = acc[nt][cc];
                if (pba.y != bk2)      va = MNEG;
                else if (pba.x == pk)  va = -10000.0f;
                else if (pba.x < pk)   va = MNEG;
                if (cnta > 1) va -= __logf((float)cnta);
                float vb = acc[nt][2 + cc];
                if (pbb.y != bk2)      vb = MNEG;
                else if (pbb.x == pk)  vb = -10000.0f;
                else if (pbb.x < pk)   vb = MNEG;
                if (cntb > 1) vb -= __logf((float)cntb);
                SPf[ra*132 + z] = va;
                SPf[rb*132 + z] = vb;
            }
        }
    }
    __syncthreads();

    // ---- E2: softmax per query row (unnormalized exp in SP, sinv + lse out) ----
    {
#pragma unroll
        for (int rr = 0; rr < 8; rr++) {
            int q = w*8 + rr;
            float4 vv = *(float4*)&SPf[q*132 + lane*4];
            float m = fmaxf(fmaxf(vv.x, vv.y), fmaxf(vv.z, vv.w));
#pragma unroll
            for (int off = 16; off >= 1; off >>= 1)
                m = fmaxf(m, __shfl_xor_sync(0xffffffffu, m, off));
            float4 e;
            e.x = __expf(vv.x - m); e.y = __expf(vv.y - m);
            e.z = __expf(vv.z - m); e.w = __expf(vv.w - m);
            float s = e.x + e.y + e.z + e.w;
#pragma unroll
            for (int off = 16; off >= 1; off >>= 1)
                s += __shfl_xor_sync(0xffffffffu, s, off);
            *(float4*)&SPf[q*132 + lane*4] = e;
            if (lane == 0) {
                sinv[q] = 1.0f / s;
                g_lse[b*NSLOT + c*CHUNK + q] = m + __logf(s);
            }
        }
    }
    __syncthreads();

    // ---- E3: pack P hi/lo into [64][136] rows (aliases dead K region) ----
    {
        int q = tid >> 2, part = tid & 3;
        char* dstH = smem + PH_OFF + q*RS + part*64;
        char* dstL = smem + PL_OFF + q*RS + part*64;
#pragma unroll
        for (int c8 = 0; c8 < 4; c8++) {
            int z0 = part*32 + c8*8;
            float4 a = *(float4*)&SPf[q*132 + z0];
            float4 d = *(float4*)&SPf[q*132 + z0 + 4];
            float f[8] = {a.x,a.y,a.z,a.w,d.x,d.y,d.z,d.w};
            uint32_t hi[4], lo[4];
#pragma unroll
            for (int e = 0; e < 4; e++) {
                __nv_bfloat16 h0 = __float2bfloat16_rn(f[e*2]);
                __nv_bfloat16 h1 = __float2bfloat16_rn(f[e*2+1]);
                __nv_bfloat162 hh; hh.x = h0; hh.y = h1; hi[e] = *(uint32_t*)&hh;
                lo[e] = pack_bf2(f[e*2] - __bfloat162float(h0), f[e*2+1] - __bfloat162float(h1));
            }
            *(uint4*)(dstH + c8*16) = make_uint4(hi[0],hi[1],hi[2],hi[3]);
            *(uint4*)(dstL + c8*16) = make_uint4(lo[0],lo[1],lo[2],lo[3]);
        }
    }
    __syncthreads();

    // ---- GEMM2: O[64q x 128d] = P . V  (V row-major, B frags via ldmatrix.trans) ----
#pragma unroll
    for (int nt = 0; nt < 8; nt++)
#pragma unroll
        for (int e = 0; e < 4; e++) acc[nt][e] = 0.f;
    {
        uint32_t paH = sb + PH_OFF + (q0+arow)*RS + akoff*2;
        uint32_t paL = sb + PL_OFF + (q0+arow)*RS + akoff*2;
        // trans B: lanes 0-7 z rows +0..7 (k-half 0), 8-15 z rows +8..15 (k-half 1), 16-31 same at d+8
        int vrow = (lane & 7) + ((lane >> 3) & 1) * 8;
        int vd   = (lane >> 4) * 8;
        uint32_t vbH = sb + VH_OFF + vrow*RS + (zbase + vd)*2;
        uint32_t vbL = sb + VL_OFF + vrow*RS + (zbase + vd)*2;
#pragma unroll
        for (int ks = 0; ks < 8; ks++) {
            uint32_t aH0,aH1,aH2,aH3, aL0,aL1,aL2,aL3;
            ldsm_x4(paH + ks*32, aH0,aH1,aH2,aH3);
            ldsm_x4(paL + ks*32, aL0,aL1,aL2,aL3);
#pragma unroll
            for (int p = 0; p < 4; p++) {
                uint32_t bH0,bH1,bH2,bH3, bL0,bL1,bL2,bL3;
                ldsm_x4_t(vbH + ks*(16*RS) + p*32, bH0,bH1,bH2,bH3);
                ldsm_x4_t(vbL + ks*(16*RS) + p*32, bL0,bL1,bL2,bL3);
                mma16816(acc[2*p],   aH0,aH1,aH2,aH3, bH0,bH1);
                mma16816(acc[2*p],   aH0,aH1,aH2,aH3, bL0,bL1);
                mma16816(acc[2*p],   aL0,aL1,aL2,aL3, bH0,bH1);
                mma16816(acc[2*p+1], aH0,aH1,aH2,aH3, bH2,bH3);
                mma16816(acc[2*p+1], aH0,aH1,aH2,aH3, bL2,bL3);
                mma16816(acc[2*p+1], aL0,aL1,aL2,aL3, bH2,bH3);
            }
        }
    }
    __syncthreads();   // SP (exp values) fully consumed -> reuse for O staging

    // ---- stage O into SP[q][d] with sinv scaling ----
    {
        int ra = q0 + (lane >> 2);
        int rb = ra + 8;
        float sa = sinv[ra], sbv = sinv[rb];
#pragma unroll
        for (int nt = 0; nt < 8; nt++) {
            int d = zbase + nt*8 + ((lane & 3) << 1);
            *(float2*)&SPf[ra*132 + d] = make_float2(acc[nt][0]*sa, acc[nt][1]*sa);
            *(float2*)&SPf[rb*132 + d] = make_float2(acc[nt][2]*sbv, acc[nt][3]*sbv);
        }
    }
    __syncthreads();

    // ---- coalesced write to g_bo ----
    {
        int q = tid >> 2, part = tid & 3;
        float* dst = &g_bo[((size_t)b*NSLOT + c*CHUNK + q)*DIM + part*32];
#pragma unroll
        for (int i = 0; i < 8; i++)
            ((float4*)dst)[i] = *(float4*)&SPf[q*132 + part*32 + i*4];
    }
}

// ===================== K4: un-sort + combine =====================
__global__ void k_combine(float* __restrict__ out) {
    int pb = blockIdx.x;
    int b  = pb >> 12;
    int tid = threadIdx.x;
    __shared__ int   sslot[8];
    __shared__ float slse[8];
    if (tid < 8) {
        int slot = g_slotof[pb*NHASH + tid];
        sslot[tid] = slot;
        slse[tid]  = g_lse[b*NSLOT + slot];
    }
    __syncthreads();
    float m = slse[0];
#pragma unroll
    for (int h = 1; h < 8; h++) m = fmaxf(m, slse[h]);
    float w[8], wsum = 0.f;
#pragma unroll
    for (int h = 0; h < 8; h++) { w[h] = __expf(slse[h] - m); wsum += w[h]; }
    float inv = 1.0f / wsum;
    float acc = 0.f;
#pragma unroll
    for (int h = 0; h < 8; h++)
        acc += w[h] * g_bo[((size_t)b*NSLOT + sslot[h]) * DIM + tid];
    out[(size_t)pb*DIM + tid] = acc * inv;
}

// ===================== launcher =====================
extern "C" void kernel_launch(void* const* d_in, const int* in_sizes, int n_in,
                              void* d_out, int out_size) {
    const float* qk  = (const float*)d_in[0];
    const float* v   = (const float*)d_in[1];
    const float* rot = (const float*)d_in[2];
    float* out = (float*)d_out;

    const int HASH_SMEM = (32768 + 4096) * 4;
    const int SCAT_SMEM = 64 * 257 * 4;

    cudaFuncSetAttribute(k_hash,    cudaFuncAttributeMaxDynamicSharedMemorySize, HASH_SMEM);
    cudaFuncSetAttribute(k_scatter, cudaFuncAttributeMaxDynamicSharedMemorySize, SCAT_SMEM);
    cudaFuncSetAttribute(k_attn_tc, cudaFuncAttributeMaxDynamicSharedMemorySize, ATTN_SMEM);

    void* cptr = nullptr;
    cudaGetSymbolAddress(&cptr, g_counts);
    cudaMemsetAsync(cptr, 0, sizeof(int) * NBATCH * 512, 0);

    k_hash   <<<(NBATCH*SEQ)/32, 256, HASH_SMEM>>>(qk, rot);
    k_hist   <<<(NBATCH*NHASH*SEQ)/256, 256>>>();
    k_prefix <<<NBATCH, 512>>>();
    k_scatter<<<NBATCH*NHASH, 256, SCAT_SMEM>>>();
    k_attn_tc<<<NBATCH*NCHUNK, 256, ATTN_SMEM>>>(qk, v);
    k_combine<<<NBATCH*SEQ, 128>>>(out);
}

// round 13
// speedup vs baseline: 1.8434x; 1.1327x over previous
#include <cuda_runtime.h>
#include <cuda_bf16.h>
#include <math.h>
#include <float.h>
#include <stdint.h>

#define NBATCH 8
#define SEQ    4096
#define DIM    128
#define NHASH  8
#define NBUCK  64
#define NCHUNK 512
#define NSLOT  32768
#define CHUNK  64
#define QKSCALE 0.08838834764831843f
#define MNEG   (-3.402823466e38f)

__device__ int   g_buckets[NBATCH*NHASH*SEQ];
__device__ int   g_counts [NBATCH*512];
__device__ int   g_bstart [NBATCH*512];
__device__ int   g_st     [NBATCH*NSLOT];
__device__ int   g_sb     [NBATCH*NSLOT];
__device__ int   g_slotof [NBATCH*SEQ*NHASH];
__device__ int   g_L      [NBATCH*SEQ*NHASH];
__device__ float g_lse    [NBATCH*NSLOT];
__device__ float g_bo     [(size_t)NBATCH*NSLOT*DIM];

// ===================== helpers =====================
__device__ __forceinline__ uint32_t smem_to_u32(const void* p) {
    uint32_t a;
    asm("{ .reg .u64 t; cvta.to.shared.u64 t, %1; cvt.u32.u64 %0, t; }" : "=r"(a) : "l"(p));
    return a;
}
__device__ __forceinline__ uint32_t pack_bf2(float a, float b) {
    __nv_bfloat162 t;
    t.x = __float2bfloat16_rn(a);
    t.y = __float2bfloat16_rn(b);
    return *(uint32_t*)&t;
}
__device__ __forceinline__ void ldsm_x4(uint32_t addr, uint32_t& r0, uint32_t& r1, uint32_t& r2, uint32_t& r3) {
    asm volatile("ldmatrix.sync.aligned.m8n8.x4.shared.b16 {%0,%1,%2,%3}, [%4];"
                 : "=r"(r0), "=r"(r1), "=r"(r2), "=r"(r3) : "r"(addr));
}
__device__ __forceinline__ void ldsm_x4_t(uint32_t addr, uint32_t& r0, uint32_t& r1, uint32_t& r2, uint32_t& r3) {
    asm volatile("ldmatrix.sync.aligned.m8n8.x4.trans.shared.b16 {%0,%1,%2,%3}, [%4];"
                 : "=r"(r0), "=r"(r1), "=r"(r2), "=r"(r3) : "r"(addr));
}
__device__ __forceinline__ void mma16816(float* c, uint32_t a0, uint32_t a1, uint32_t a2, uint32_t a3,
                                         uint32_t b0, uint32_t b1) {
    asm volatile("mma.sync.aligned.m16n8k16.row.col.f32.bf16.bf16.f32 "
                 "{%0,%1,%2,%3}, {%4,%5,%6,%7}, {%8,%9}, {%0,%1,%2,%3};"
                 : "+f"(c[0]), "+f"(c[1]), "+f"(c[2]), "+f"(c[3])
                 : "r"(a0), "r"(a1), "r"(a2), "r"(a3), "r"(b0), "r"(b1));
}

// ===================== K1: LSH hashing =====================
__global__ void k_hash(const float* __restrict__ qk, const float* __restrict__ rot) {
    extern __shared__ float sm[];
    float* srot = sm;
    float* sq   = sm + 32768;
    int tid = threadIdx.x;
    for (int i = tid; i < 32768/4; i += 256)
        ((float4*)srot)[i] = ((const float4*)rot)[i];
    int tok0 = blockIdx.x * 32;
    int b = tok0 >> 12;
    int s0 = tok0 & 4095;
    const float* qbase = qk + (size_t)tok0 * DIM;
    for (int i = tid; i < (32*128)/4; i += 256)
        ((float4*)sq)[i] = ((const float4*)qbase)[i];
    __syncthreads();

    int ngrp = tid & 31, tgrp = tid >> 5;
    int hub = ngrp * 8, tb = tgrp * 4;
    float acc[4][8];
#pragma unroll
    for (int i = 0; i < 4; i++)
#pragma unroll
        for (int j = 0; j < 8; j++) acc[i][j] = 0.f;
#pragma unroll 4
    for (int d = 0; d < 128; d++) {
        float4 r0 = *(const float4*)(srot + d*256 + hub);
        float4 r1 = *(const float4*)(srot + d*256 + hub + 4);
#pragma unroll
        for (int i = 0; i < 4; i++) {
            float q = sq[(tb+i)*128 + d];
            acc[i][0] += q*r0.x; acc[i][1] += q*r0.y; acc[i][2] += q*r0.z; acc[i][3] += q*r0.w;
            acc[i][4] += q*r1.x; acc[i][5] += q*r1.y; acc[i][6] += q*r1.z; acc[i][7] += q*r1.w;
        }
    }
    int h = ngrp >> 2, k = ngrp & 3;
#pragma unroll
    for (int i = 0; i < 4; i++) {
        float bv = -1.0f; int bi = 0;
#pragma unroll
        for (int j = 0; j < 8; j++) {
            float r = acc[i][j];
            float a = fabsf(r);
            int n  = k*8 + j;
            int ci = (r < 0.f) ? (n + 32) : n;
            if (a > bv || (a == bv && ci < bi)) { bv = a; bi = ci; }
        }
#pragma unroll
        for (int off = 1; off <= 2; off <<= 1) {
            float ov = __shfl_xor_sync(0xffffffffu, bv, off);
            int   oi = __shfl_xor_sync(0xffffffffu, bi, off);
            if (ov > bv || (ov == bv && oi < bi)) { bv = ov; bi = oi; }
        }
        if (k == 0)
            g_buckets[((b*NHASH + h) * SEQ) + s0 + tb + i] = h*NBUCK + bi;
    }
}

// ===================== K2: counting sort =====================
__global__ void k_hist() {
    int i = blockIdx.x * 256 + threadIdx.x;
    int b = i >> 15;
    atomicAdd(&g_counts[b*512 + g_buckets[i]], 1);
}
__global__ void k_prefix() {
    __shared__ int sc[512];
    int b = blockIdx.x, t = threadIdx.x;
    int v = g_counts[b*512 + t];
    sc[t] = v;
    __syncthreads();
    for (int off = 1; off < 512; off <<= 1) {
        int add = (t >= off) ? sc[t-off] : 0;
        __syncthreads();
        sc[t] += add;
        __syncthreads();
    }
    g_bstart[b*512 + t] = sc[t] - v;
}
__global__ void k_scatter() {
    extern __shared__ int sh[];
    int b = blockIdx.x >> 3, h = blockIdx.x & 7;
    int t = threadIdx.x;
    const int* bk = &g_buckets[(b*NHASH + h) * SEQ];
    for (int i = t; i < 64*257; i += 256) sh[i] = 0;
    __syncthreads();
    int p0 = t * 16;
#pragma unroll
    for (int q = 0; q < 16; q++) {
        int c = bk[p0 + q] - h*NBUCK;
        sh[c*257 + t]++;
    }
    __syncthreads();
    if (t < 64) {
        int run = g_bstart[b*512 + h*NBUCK + t];
        for (int u = 0; u < 256; u++) {
            int v = sh[t*257 + u];
            sh[t*257 + u] = run;
            run += v;
        }
    }
    __syncthreads();
#pragma unroll
    for (int q = 0; q < 16; q++) {
        int pos = p0 + q;
        int Bg  = bk[pos];
        int c   = Bg - h*NBUCK;
        int slot = sh[c*257 + t]++;
        g_st[b*NSLOT + slot] = pos;
        g_sb[b*NSLOT + slot] = Bg;
        g_slotof[(b*SEQ + pos)*NHASH + h] = slot;
        g_L     [(b*SEQ + pos)*NHASH + h] = Bg*512 + (slot >> 6);
    }
}

// ===================== K3: occupancy-2 mma.sync attention =====================
// Row stride 272 B; K and V staged in 64-row halves through reused buffers.
#define RS 272
#define QH_OFF   0        // 64*272 = 17408
#define QL_OFF   17408    // ends 34816
#define SP_OFF   0        // fp32 [64][132] = 33792, aliases Q after GEMM1 completes
#define KB_H     34816    // K half buffer hi: 64*272 = 17408
#define KB_L     52224    // ends 69632
#define PH_OFF   34816    // P hi aliases KB_H after GEMM1
#define PL_OFF   52224
#define VB_H     69632    // V half buffer hi
#define VB_L     87040    // ends 104448
#define PQB_OFF  104448   // int2[64]
#define POSK_OFF 104960   // int[128]
#define BKV_OFF  105472   // int[128]
#define SLQ_OFF  105984   // int[512]
#define SLK_OFF  108032   // int[1024]
#define SINV_OFF 112128   // float[64]
#define ATTN_SMEM 112640

__global__ __launch_bounds__(256, 2) void k_attn_tc(const float* __restrict__ qk,
                                                    const float* __restrict__ vin) {
    extern __shared__ char smem[];
    uint32_t sb = smem_to_u32(smem);
    int tid = threadIdx.x;
    int w   = tid >> 5, lane = tid & 31;

    int bid = blockIdx.x;
    int b = bid >> 9;
    int c = bid & 511;
    int cprev = (c + NCHUNK - 1) & 511;

    int2*  pqb  = (int2*)(smem + PQB_OFF);
    int*   posk = (int*)(smem + POSK_OFF);
    int*   bkv  = (int*)(smem + BKV_OFF);
    int*   sLq  = (int*)(smem + SLQ_OFF);
    int*   sLk  = (int*)(smem + SLK_OFF);
    float* sinv = (float*)(smem + SINV_OFF);
    float* SPf  = (float*)(smem + SP_OFF);

    // ---- metadata gather ----
    if (tid < 64) {
        int slot = c*CHUNK + tid;
        int pos  = g_st[b*NSLOT + slot];
        pqb[tid] = make_int2(pos, g_sb[b*NSLOT + slot]);
        const int4* lp = (const int4*)&g_L[(b*SEQ + pos)*NHASH];
        ((int4*)(sLq + tid*8))[0] = lp[0];
        ((int4*)(sLq + tid*8))[1] = lp[1];
    } else if (tid < 192) {
        int z = tid - 64;
        int slot = (z < 64) ? (c*CHUNK + z) : (cprev*CHUNK + (z - 64));
        int pos  = g_st[b*NSLOT + slot];
        posk[z] = pos;
        bkv[z]  = g_sb[b*NSLOT + slot];
        const int4* lp = (const int4*)&g_L[(b*SEQ + pos)*NHASH];
        ((int4*)(sLk + z*8))[0] = lp[0];
        ((int4*)(sLk + z*8))[1] = lp[1];
    }
    __syncthreads();

    int rowq = tid >> 2, part = tid & 3;   // 4 threads per row, 32 elems each

    // ---- stage Q (hi/lo), scaled ----
    {
        const float* src = qk + ((size_t)b*SEQ + pqb[rowq].x)*DIM + part*32;
        char* dstH = smem + QH_OFF + rowq*RS + part*64;
        char* dstL = smem + QL_OFF + rowq*RS + part*64;
#pragma unroll
        for (int c8 = 0; c8 < 4; c8++) {
            float4 a = ((const float4*)src)[c8*2];
            float4 d = ((const float4*)src)[c8*2 + 1];
            float f[8] = {a.x,a.y,a.z,a.w,d.x,d.y,d.z,d.w};
            uint32_t hi[4], lo[4];
#pragma unroll
            for (int e = 0; e < 4; e++) {
                float v0 = f[e*2]   * QKSCALE;
                float v1 = f[e*2+1] * QKSCALE;
                __nv_bfloat16 h0 = __float2bfloat16_rn(v0);
                __nv_bfloat16 h1 = __float2bfloat16_rn(v1);
                __nv_bfloat162 hh; hh.x = h0; hh.y = h1; hi[e] = *(uint32_t*)&hh;
                lo[e] = pack_bf2(v0 - __bfloat162float(h0), v1 - __bfloat162float(h1));
            }
            *(uint4*)(dstH + c8*16) = make_uint4(hi[0],hi[1],hi[2],hi[3]);
            *(uint4*)(dstL + c8*16) = make_uint4(lo[0],lo[1],lo[2],lo[3]);
        }
    }

    // warp tile constants
    int q0 = (w & 3) << 4;
    int zq = (w >> 2) << 5;    // 32-z block within staged half (GEMM1)
    int db = (w >> 2) << 6;    // 64-d block (GEMM2)

    // A-fragment addressing (non-trans x4)
    int arow  = (lane & 7) + ((lane >> 3) & 1) * 8;
    int akoff = (lane >> 4) * 8;
    uint32_t aoffH = sb + QH_OFF + (q0+arow)*RS + akoff*2;
    uint32_t aoffL = sb + QL_OFF + (q0+arow)*RS + akoff*2;
    // GEMM1 B addressing in K half buffer
    int brow = (lane & 7) + (lane >> 4) * 8;
    int bk   = ((lane >> 3) & 1) * 8;
    uint32_t boffH = sb + KB_H + (zq + brow)*RS + bk*2;
    uint32_t boffL = sb + KB_L + (zq + brow)*RS + bk*2;

    float acc[8][4];
#pragma unroll
    for (int nt = 0; nt < 8; nt++)
#pragma unroll
        for (int e = 0; e < 4; e++) acc[nt][e] = 0.f;

    // ---- GEMM1: two z-half passes, K restaged between ----
#pragma unroll
    for (int s = 0; s < 2; s++) {
        // stage K rows [s*64, s*64+64) normalized hi/lo
        {
            int z = s*64 + rowq;
            const float* src = qk + ((size_t)b*SEQ + posk[z])*DIM + part*32;
            float ss = 0.f;
            float4 fv[8];
#pragma unroll
            for (int k4 = 0; k4 < 8; k4++) {
                fv[k4] = ((const float4*)src)[k4];
                ss += fv[k4].x*fv[k4].x + fv[k4].y*fv[k4].y + fv[k4].z*fv[k4].z + fv[k4].w*fv[k4].w;
            }
            ss += __shfl_xor_sync(0xffffffffu, ss, 1);
            ss += __shfl_xor_sync(0xffffffffu, ss, 2);
            float rscv = 1.0f / fmaxf(sqrtf(ss), 1e-12f);
            char* dstH = smem + KB_H + rowq*RS + part*64;
            char* dstL = smem + KB_L + rowq*RS + part*64;
#pragma unroll
            for (int c8 = 0; c8 < 4; c8++) {
                float f[8] = {fv[c8*2].x, fv[c8*2].y, fv[c8*2].z, fv[c8*2].w,
                              fv[c8*2+1].x, fv[c8*2+1].y, fv[c8*2+1].z, fv[c8*2+1].w};
                uint32_t hi[4], lo[4];
#pragma unroll
                for (int e = 0; e < 4; e++) {
                    float v0 = f[e*2]   * rscv;
                    float v1 = f[e*2+1] * rscv;
                    __nv_bfloat16 h0 = __float2bfloat16_rn(v0);
                    __nv_bfloat16 h1 = __float2bfloat16_rn(v1);
                    __nv_bfloat162 hh; hh.x = h0; hh.y = h1; hi[e] = *(uint32_t*)&hh;
                    lo[e] = pack_bf2(v0 - __bfloat162float(h0), v1 - __bfloat162float(h1));
                }
                *(uint4*)(dstH + c8*16) = make_uint4(hi[0],hi[1],hi[2],hi[3]);
                *(uint4*)(dstL + c8*16) = make_uint4(lo[0],lo[1],lo[2],lo[3]);
            }
        }
        __syncthreads();
        // MMA pass: acc[s*4 + 0..3]
#pragma unroll
        for (int ks = 0; ks < 8; ks++) {
            uint32_t aH0,aH1,aH2,aH3, aL0,aL1,aL2,aL3;
            ldsm_x4(aoffH + ks*32, aH0,aH1,aH2,aH3);
            ldsm_x4(aoffL + ks*32, aL0,aL1,aL2,aL3);
#pragma unroll
            for (int p = 0; p < 2; p++) {
                uint32_t bH0,bH1,bH2,bH3, bL0,bL1,bL2,bL3;
                ldsm_x4(boffH + p*(16*RS) + ks*32, bH0,bH1,bH2,bH3);
                ldsm_x4(boffL + p*(16*RS) + ks*32, bL0,bL1,bL2,bL3);
                float* c0 = acc[s*4 + 2*p];
                float* c1 = acc[s*4 + 2*p + 1];
                mma16816(c0, aH0,aH1,aH2,aH3, bH0,bH1);
                mma16816(c0, aH0,aH1,aH2,aH3, bL0,bL1);
                mma16816(c0, aL0,aL1,aL2,aL3, bH0,bH1);
                mma16816(c1, aH0,aH1,aH2,aH3, bH2,bH3);
                mma16816(c1, aH0,aH1,aH2,aH3, bL2,bL3);
                mma16816(c1, aL0,aL1,aL2,aL3, bH2,bH3);
            }
        }
        __syncthreads();
    }

    // ---- E1: masks + dup-count; write SP[q][z] (aliases dead Q) ----
    {
        int ra = q0 + (lane >> 2);
        int rb = ra + 8;
        int2 pba = pqb[ra], pbb = pqb[rb];
        int lqa[8], lqb[8];
#pragma unroll
        for (int h = 0; h < 8; h++) { lqa[h] = sLq[ra*8 + h]; lqb[h] = sLq[rb*8 + h]; }
#pragma unroll
        for (int a = 0; a < 8; a++) {
            int p1 = a >> 2, j = a & 3;
#pragma unroll
            for (int cc = 0; cc < 2; cc++) {
                int z = p1*64 + zq + j*8 + ((lane & 3) << 1) + cc;
                int pk = posk[z];
                int bk2 = bkv[z];
                int cnta = 0, cntb = 0;
#pragma unroll
                for (int h = 0; h < 8; h++) {
                    int lkv = sLk[z*8 + h];
                    int l2  = (lkv & ~511) | ((lkv + 1) & 511);
                    cnta += (lqa[h] == lkv) + (lqa[h] == l2);
                    cntb += (lqb[h] == lkv) + (lqb[h] == l2);
                }
                float va = acc[a][cc];
                if (pba.y != bk2)      va = MNEG;
                else if (pba.x == pk)  va = -10000.0f;
                else if (pba.x < pk)   va = MNEG;
                if (cnta > 1) va -= __logf((float)cnta);
                float vb = acc[a][2 + cc];
                if (pbb.y != bk2)      vb = MNEG;
                else if (pbb.x == pk)  vb = -10000.0f;
                else if (pbb.x < pk)   vb = MNEG;
                if (cntb > 1) vb -= __logf((float)cntb);
                SPf[ra*132 + z] = va;
                SPf[rb*132 + z] = vb;
            }
        }
    }
    __syncthreads();

    // ---- E2: softmax per query row ----
    {
#pragma unroll
        for (int rr = 0; rr < 8; rr++) {
            int q = w*8 + rr;
            float4 vv = *(float4*)&SPf[q*132 + lane*4];
            float m = fmaxf(fmaxf(vv.x, vv.y), fmaxf(vv.z, vv.w));
#pragma unroll
            for (int off = 16; off >= 1; off >>= 1)
                m = fmaxf(m, __shfl_xor_sync(0xffffffffu, m, off));
            float4 e;
            e.x = __expf(vv.x - m); e.y = __expf(vv.y - m);
            e.z = __expf(vv.z - m); e.w = __expf(vv.w - m);
            float s = e.x + e.y + e.z + e.w;
#pragma unroll
            for (int off = 16; off >= 1; off >>= 1)
                s += __shfl_xor_sync(0xffffffffu, s, off);
            *(float4*)&SPf[q*132 + lane*4] = e;
            if (lane == 0) {
                sinv[q] = 1.0f / s;
                g_lse[b*NSLOT + c*CHUNK + q] = m + __logf(s);
            }
        }
    }
    __syncthreads();

    // ---- E3: pack P hi/lo (aliases dead K buffer) ----
    {
        char* dstH = smem + PH_OFF + rowq*RS + part*64;
        char* dstL = smem + PL_OFF + rowq*RS + part*64;
#pragma unroll
        for (int c8 = 0; c8 < 4; c8++) {
            int z0 = part*32 + c8*8;
            float4 a = *(float4*)&SPf[rowq*132 + z0];
            float4 d = *(float4*)&SPf[rowq*132 + z0 + 4];
            float f[8] = {a.x,a.y,a.z,a.w,d.x,d.y,d.z,d.w};
            uint32_t hi[4], lo[4];
#pragma unroll
            for (int e = 0; e < 4; e++) {
                __nv_bfloat16 h0 = __float2bfloat16_rn(f[e*2]);
                __nv_bfloat16 h1 = __float2bfloat16_rn(f[e*2+1]);
                __nv_bfloat162 hh; hh.x = h0; hh.y = h1; hi[e] = *(uint32_t*)&hh;
                lo[e] = pack_bf2(f[e*2] - __bfloat162float(h0), f[e*2+1] - __bfloat162float(h1));
            }
            *(uint4*)(dstH + c8*16) = make_uint4(hi[0],hi[1],hi[2],hi[3]);
            *(uint4*)(dstL + c8*16) = make_uint4(lo[0],lo[1],lo[2],lo[3]);
        }
    }

    // ---- GEMM2: two z-half passes over reused V buffer ----
#pragma unroll
    for (int nt = 0; nt < 8; nt++)
#pragma unroll
        for (int e = 0; e < 4; e++) acc[nt][e] = 0.f;

    uint32_t paH = sb + PH_OFF + (q0+arow)*RS + akoff*2;
    uint32_t paL = sb + PL_OFF + (q0+arow)*RS + akoff*2;
    int vrow = (lane & 7) + ((lane >> 3) & 1) * 8;
    int vd   = (lane >> 4) * 8;
    uint32_t vbH = sb + VB_H + vrow*RS + (db + vd)*2;
    uint32_t vbL = sb + VB_L + vrow*RS + (db + vd)*2;

#pragma unroll
    for (int s = 0; s < 2; s++) {
        // stage V rows [s*64, s*64+64) hi/lo
        {
            int z = s*64 + rowq;
            const float* src = vin + ((size_t)b*SEQ + posk[z])*DIM + part*32;
            char* dstH = smem + VB_H + rowq*RS + part*64;
            char* dstL = smem + VB_L + rowq*RS + part*64;
#pragma unroll
            for (int c8 = 0; c8 < 4; c8++) {
                float4 a = ((const float4*)src)[c8*2];
                float4 d = ((const float4*)src)[c8*2 + 1];
                float f[8] = {a.x,a.y,a.z,a.w,d.x,d.y,d.z,d.w};
                uint32_t hi[4], lo[4];
#pragma unroll
                for (int e = 0; e < 4; e++) {
                    __nv_bfloat16 h0 = __float2bfloat16_rn(f[e*2]);
                    __nv_bfloat16 h1 = __float2bfloat16_rn(f[e*2+1]);
                    __nv_bfloat162 hh; hh.x = h0; hh.y = h1; hi[e] = *(uint32_t*)&hh;
                    lo[e] = pack_bf2(f[e*2] - __bfloat162float(h0), f[e*2+1] - __bfloat162float(h1));
                }
                *(uint4*)(dstH + c8*16) = make_uint4(hi[0],hi[1],hi[2],hi[3]);
                *(uint4*)(dstL + c8*16) = make_uint4(lo[0],lo[1],lo[2],lo[3]);
            }
        }
        __syncthreads();
        // MMA pass: k covers z in [s*64, s*64+64)
#pragma unroll
        for (int kc = 0; kc < 4; kc++) {
            uint32_t aH0,aH1,aH2,aH3, aL0,aL1,aL2,aL3;
            ldsm_x4(paH + (s*4 + kc)*32, aH0,aH1,aH2,aH3);
            ldsm_x4(paL + (s*4 + kc)*32, aL0,aL1,aL2,aL3);
#pragma unroll
            for (int p = 0; p < 4; p++) {
                uint32_t bH0,bH1,bH2,bH3, bL0,bL1,bL2,bL3;
                ldsm_x4_t(vbH + kc*(16*RS) + p*32, bH0,bH1,bH2,bH3);
                ldsm_x4_t(vbL + kc*(16*RS) + p*32, bL0,bL1,bL2,bL3);
                float* c0 = acc[2*p];
                float* c1 = acc[2*p + 1];
                mma16816(c0, aH0,aH1,aH2,aH3, bH0,bH1);
                mma16816(c0, aH0,aH1,aH2,aH3, bL0,bL1);
                mma16816(c0, aL0,aL1,aL2,aL3, bH0,bH1);
                mma16816(c1, aH0,aH1,aH2,aH3, bH2,bH3);
                mma16816(c1, aH0,aH1,aH2,aH3, bL2,bL3);
                mma16816(c1, aL0,aL1,aL2,aL3, bH2,bH3);
            }
        }
        __syncthreads();
    }

    // ---- stage O into SPf[q][d] with sinv scaling ----
    {
        int ra = q0 + (lane >> 2);
        int rb = ra + 8;
        float sa = sinv[ra], sbv = sinv[rb];
#pragma unroll
        for (int nt = 0; nt < 8; nt++) {
            int d = db + nt*8 + ((lane & 3) << 1);
            *(float2*)&SPf[ra*132 + d] = make_float2(acc[nt][0]*sa, acc[nt][1]*sa);
            *(float2*)&SPf[rb*132 + d] = make_float2(acc[nt][2]*sbv, acc[nt][3]*sbv);
        }
    }
    __syncthreads();

    // ---- coalesced write to g_bo ----
    {
        float* dst = &g_bo[((size_t)b*NSLOT + c*CHUNK + rowq)*DIM + part*32];
#pragma unroll
        for (int i = 0; i < 8; i++)
            ((float4*)dst)[i] = *(float4*)&SPf[rowq*132 + part*32 + i*4];
    }
}

// ===================== K4: un-sort + combine =====================
__global__ void k_combine(float* __restrict__ out) {
    int pb = blockIdx.x;
    int b  = pb >> 12;
    int tid = threadIdx.x;
    __shared__ int   sslot[8];
    __shared__ float slse[8];
    if (tid < 8) {
        int slot = g_slotof[pb*NHASH + tid];
        sslot[tid] = slot;
        slse[tid]  = g_lse[b*NSLOT + slot];
    }
    __syncthreads();
    float m = slse[0];
#pragma unroll
    for (int h = 1; h < 8; h++) m = fmaxf(m, slse[h]);
    float w[8], wsum = 0.f;
#pragma unroll
    for (int h = 0; h < 8; h++) { w[h] = __expf(slse[h] - m); wsum += w[h]; }
    float inv = 1.0f / wsum;
    float acc = 0.f;
#pragma unroll
    for (int h = 0; h < 8; h++)
        acc += w[h] * g_bo[((size_t)b*NSLOT + sslot[h]) * DIM + tid];
    out[(size_t)pb*DIM + tid] = acc * inv;
}

// ===================== launcher =====================
extern "C" void kernel_launch(void* const* d_in, const int* in_sizes, int n_in,
                              void* d_out, int out_size) {
    const float* qk  = (const float*)d_in[0];
    const float* v   = (const float*)d_in[1];
    const float* rot = (const float*)d_in[2];
    float* out = (float*)d_out;

    const int HASH_SMEM = (32768 + 4096) * 4;
    const int SCAT_SMEM = 64 * 257 * 4;

    cudaFuncSetAttribute(k_hash,    cudaFuncAttributeMaxDynamicSharedMemorySize, HASH_SMEM);
    cudaFuncSetAttribute(k_scatter, cudaFuncAttributeMaxDynamicSharedMemorySize, SCAT_SMEM);
    cudaFuncSetAttribute(k_attn_tc, cudaFuncAttributeMaxDynamicSharedMemorySize, ATTN_SMEM);

    void* cptr = nullptr;
    cudaGetSymbolAddress(&cptr, g_counts);
    cudaMemsetAsync(cptr, 0, sizeof(int) * NBATCH * 512, 0);

    k_hash   <<<(NBATCH*SEQ)/32, 256, HASH_SMEM>>>(qk, rot);
    k_hist   <<<(NBATCH*NHASH*SEQ)/256, 256>>>();
    k_prefix <<<NBATCH, 512>>>();
    k_scatter<<<NBATCH*NHASH, 256, SCAT_SMEM>>>();
    k_attn_tc<<<NBATCH*NCHUNK, 256, ATTN_SMEM>>>(qk, v);
    k_combine<<<NBATCH*SEQ, 128>>>(out);
}